// round 16
// baseline (speedup 1.0000x reference)
#include <cuda_runtime.h>
#include <cuda_fp16.h>
#include <cstdint>

#define NN   100000
#define NNZE 3200000
#define NIDX 50000
#define BKT  128          // bucket capacity per row (max degree ~60)

static inline int cdiv(int a, int b) { return (a + b - 1) / b; }

// ---------------- scratch (device globals; zero-initialized at module load) ----
__device__ int    g_cursor[NN];     // degree counters; cleared in gather_out
__device__ int    g_mark[NN];       // set in scatter_prep, cleared by final_rows
__device__ int4   g_bkt4[(size_t)NN * (BKT / 2)];   // 2 edges per int4; unused = 0
// fp16 basis: [N][384] = [x | T1 | T2]
__device__ __half g_Bh[(size_t)NN * 384];
// fp16 hidden: [N][256]
__device__ __half g_Hh[(size_t)NN * 256];
// fp16 Z: [N][128]  ([0:64)=U, [64:128)=V)
__device__ __half g_Zh[(size_t)NN * 128];
// fp16 Q = U + 2*(L V): [N][64]
__device__ __half g_Qh[(size_t)NN * 64];
// P = H @ (W2_0 - W2_2) + b2, fp32; final pass accumulates in place
__device__ float  g_P[(size_t)NN * 64];
// fp16 transposed weights (n-major, K contiguous)
__device__ __half g_W1t[256 * 384];
__device__ __half g_W2catT[128 * 256];
__device__ __half g_W2dT[64 * 256];

// ---------------- packed f32x2 helpers ---------------------------------------
__device__ __forceinline__ unsigned long long pack2(float v) {
    unsigned long long r;
    asm("mov.b64 %0, {%1, %1};" : "=l"(r) : "f"(v));
    return r;
}
__device__ __forceinline__ unsigned long long h2f2(uint32_t h) {
    unsigned long long r;
    asm("{\n\t"
        ".reg .b16 l, h;\n\t"
        ".reg .f32 fl, fh;\n\t"
        "mov.b32 {l, h}, %1;\n\t"
        "cvt.f32.f16 fl, l;\n\t"
        "cvt.f32.f16 fh, h;\n\t"
        "mov.b64 %0, {fl, fh};\n\t"
        "}" : "=l"(r) : "r"(h));
    return r;
}
__device__ __forceinline__ void fma2(unsigned long long& acc,
                                     unsigned long long a, unsigned long long b) {
    asm("fma.rn.f32x2 %0, %1, %2, %0;" : "+l"(acc) : "l"(a), "l"(b));
}
__device__ __forceinline__ void add2(unsigned long long& a, unsigned long long b) {
    asm("add.rn.f32x2 %0, %0, %1;" : "+l"(a) : "l"(b));
}
__device__ __forceinline__ float2 unpack2(unsigned long long a) {
    float2 f;
    asm("mov.b64 {%0, %1}, %2;" : "=f"(f.x), "=f"(f.y) : "l"(a));
    return f;
}
__device__ __forceinline__ uint2 f4_to_h4(float4 v) {
    __half2 h0 = __floats2half2_rn(v.x, v.y);
    __half2 h1 = __floats2half2_rn(v.z, v.w);
    uint2 u;
    u.x = *reinterpret_cast<uint32_t*>(&h0);
    u.y = *reinterpret_cast<uint32_t*>(&h1);
    return u;
}

// ---------------- cp.async helpers --------------------------------------------
__device__ __forceinline__ void cp_async16(uint32_t dst, const void* src, int sz) {
    asm volatile("cp.async.ca.shared.global [%0], [%1], 16, %2;"
                 :: "r"(dst), "l"(src), "r"(sz));
}
__device__ __forceinline__ void cp_commit() {
    asm volatile("cp.async.commit_group;");
}
template <int NWAIT>
__device__ __forceinline__ void cp_wait() {
    asm volatile("cp.async.wait_group %0;" :: "n"(NWAIT));
}

// ---------------- scatter + x->fp16 + weight prep + marking (one launch) -------
__global__ void scatter_prep_kernel(const int* __restrict__ rows,
                                    const int* __restrict__ cols,
                                    const float* __restrict__ vals,
                                    const float* __restrict__ x,
                                    const float* __restrict__ W1,
                                    const float* __restrict__ W2,
                                    const int* __restrict__ idx) {
    int i = blockIdx.x * blockDim.x + threadIdx.x;
    if (i < NNZE) {
        int r = rows[i];
        int pos = atomicAdd(&g_cursor[r], 1);
        reinterpret_cast<int2*>(g_bkt4)[(size_t)r * BKT + pos] =
            make_int2(cols[i], __float_as_int(vals[i]));
    }
    if (i < NN * 32) {
        int n = i >> 5, f4 = i & 31;
        float4 v = reinterpret_cast<const float4*>(x)[i];
        reinterpret_cast<uint2*>(g_Bh + (size_t)n * 384)[f4] = f4_to_h4(v);
    }
    if (i < 256 * 384) {              // W1t[j][t], t = k*128+f
        int j = i / 384, t = i % 384;
        int k = t / 128, f = t % 128;
        g_W1t[i] = __float2half(W1[(f * 3 + k) * 256 + j]);
    }
    if (i < 128 * 256) {              // W2catT[j][f]
        int j = i / 256, f = i % 256;
        int kk = (j < 64) ? 1 : 2;
        int jj = (j < 64) ? j : (j - 64);
        g_W2catT[i] = __float2half(W2[(f * 3 + kk) * 64 + jj]);
    }
    if (i < 64 * 256) {               // W2dT[j][f] = W2_0 - W2_2
        int j = i / 256, f = i % 256;
        g_W2dT[i] = __float2half(W2[(f * 3 + 0) * 64 + j] - W2[(f * 3 + 2) * 64 + j]);
    }
    if (i < NIDX) g_mark[idx[i]] = 1;
}

// ---------------- SpMM over fp16 basis: half-warp edge pairing -----------------
template <bool SUB>
__global__ void spmm_bh_kernel(int src_off, int dst_off) {
    int gw = (blockIdx.x * blockDim.x + threadIdx.x) >> 5;
    if (gw >= NN) return;
    int lane = threadIdx.x & 31;
    int hi = lane >> 4;          // which edge of each pair
    int sub = lane & 15;         // 16B feature slice
    int n = g_cursor[gw];
    const int4* b4 = g_bkt4 + (size_t)gw * (BKT / 2);

    unsigned long long acc[4] = {0ull, 0ull, 0ull, 0ull};

    int iters = (n + 7) >> 3;    // buckets zero-padded -> no tail loop
    for (int it = 0; it < iters; it++) {
        int4 e[4];
        #pragma unroll
        for (int q = 0; q < 4; q++) e[q] = b4[it * 4 + q];
        #pragma unroll
        for (int q = 0; q < 4; q++) {
            int col   = hi ? e[q].z : e[q].x;
            int vbits = hi ? e[q].w : e[q].y;
            uint4 u = *reinterpret_cast<const uint4*>(
                g_Bh + (size_t)col * 384 + src_off + sub * 8);
            unsigned long long v2 = pack2(__int_as_float(vbits));
            fma2(acc[0], h2f2(u.x), v2);
            fma2(acc[1], h2f2(u.y), v2);
            fma2(acc[2], h2f2(u.z), v2);
            fma2(acc[3], h2f2(u.w), v2);
        }
    }
    #pragma unroll
    for (int q = 0; q < 4; q++) {
        unsigned long long o = __shfl_xor_sync(0xffffffffu, acc[q], 16);
        add2(acc[q], o);
    }
    if (hi == 0) {
        float f[8];
        #pragma unroll
        for (int q = 0; q < 4; q++) {
            float2 t = unpack2(acc[q]);
            f[2 * q] = t.x; f[2 * q + 1] = t.y;
        }
        if (SUB) {
            uint4 su = *reinterpret_cast<const uint4*>(
                g_Bh + (size_t)gw * 384 + sub * 8);
            const __half* sh = reinterpret_cast<const __half*>(&su);
            #pragma unroll
            for (int q = 0; q < 8; q++)
                f[q] = 2.f * f[q] - __half2float(sh[q]);
        }
        uint4 o;
        __half2 h0 = __floats2half2_rn(f[0], f[1]);
        __half2 h1 = __floats2half2_rn(f[2], f[3]);
        __half2 h2 = __floats2half2_rn(f[4], f[5]);
        __half2 h3 = __floats2half2_rn(f[6], f[7]);
        o.x = *reinterpret_cast<uint32_t*>(&h0);
        o.y = *reinterpret_cast<uint32_t*>(&h1);
        o.z = *reinterpret_cast<uint32_t*>(&h2);
        o.w = *reinterpret_cast<uint32_t*>(&h3);
        *reinterpret_cast<uint4*>(g_Bh + (size_t)gw * 384 + dst_off + sub * 8) = o;
    }
}

// ---------------- Q = U + 2*(L V): rows 64 halves (128B), paired edges ---------
__global__ void spmm_q_kernel() {
    int gw = (blockIdx.x * blockDim.x + threadIdx.x) >> 5;
    if (gw >= NN) return;
    int lane = threadIdx.x & 31;
    int hi = lane >> 4;
    int sub = lane & 15;         // 8B slice (4 halves)
    int n = g_cursor[gw];
    const int4* b4 = g_bkt4 + (size_t)gw * (BKT / 2);

    unsigned long long acc[2] = {0ull, 0ull};
    int iters = (n + 7) >> 3;
    for (int it = 0; it < iters; it++) {
        int4 e[4];
        #pragma unroll
        for (int q = 0; q < 4; q++) e[q] = b4[it * 4 + q];
        #pragma unroll
        for (int q = 0; q < 4; q++) {
            int col   = hi ? e[q].z : e[q].x;
            int vbits = hi ? e[q].w : e[q].y;
            uint2 u = *reinterpret_cast<const uint2*>(
                g_Zh + (size_t)col * 128 + 64 + sub * 4);
            unsigned long long v2 = pack2(__int_as_float(vbits));
            fma2(acc[0], h2f2(u.x), v2);
            fma2(acc[1], h2f2(u.y), v2);
        }
    }
    #pragma unroll
    for (int q = 0; q < 2; q++) {
        unsigned long long o = __shfl_xor_sync(0xffffffffu, acc[q], 16);
        add2(acc[q], o);
    }
    if (hi == 0) {
        float2 a0 = unpack2(acc[0]);
        float2 a1 = unpack2(acc[1]);
        uint2 uu = *reinterpret_cast<const uint2*>(
            g_Zh + (size_t)gw * 128 + sub * 4);
        const __half* uh = reinterpret_cast<const __half*>(&uu);
        __half2 h0 = __floats2half2_rn(__half2float(uh[0]) + 2.f * a0.x,
                                       __half2float(uh[1]) + 2.f * a0.y);
        __half2 h1 = __floats2half2_rn(__half2float(uh[2]) + 2.f * a1.x,
                                       __half2float(uh[3]) + 2.f * a1.y);
        uint2 o;
        o.x = *reinterpret_cast<uint32_t*>(&h0);
        o.y = *reinterpret_cast<uint32_t*>(&h1);
        *reinterpret_cast<uint2*>(g_Qh + (size_t)gw * 64 + sub * 4) = o;
    }
}

// ---------------- final: marked rows, P[r] += sum v*Q[col]; clear mark ----------
__global__ void final_rows_kernel() {
    int gw = (blockIdx.x * blockDim.x + threadIdx.x) >> 5;
    if (gw >= NN) return;
    if (g_mark[gw] == 0) return;
    int lane = threadIdx.x & 31;
    int hi = lane >> 4;
    int sub = lane & 15;
    int n = g_cursor[gw];
    const int4* b4 = g_bkt4 + (size_t)gw * (BKT / 2);

    unsigned long long acc[2] = {0ull, 0ull};
    int iters = (n + 7) >> 3;
    for (int it = 0; it < iters; it++) {
        int4 e[4];
        #pragma unroll
        for (int q = 0; q < 4; q++) e[q] = b4[it * 4 + q];
        #pragma unroll
        for (int q = 0; q < 4; q++) {
            int col   = hi ? e[q].z : e[q].x;
            int vbits = hi ? e[q].w : e[q].y;
            uint2 u = *reinterpret_cast<const uint2*>(
                g_Qh + (size_t)col * 64 + sub * 4);
            unsigned long long v2 = pack2(__int_as_float(vbits));
            fma2(acc[0], h2f2(u.x), v2);
            fma2(acc[1], h2f2(u.y), v2);
        }
    }
    #pragma unroll
    for (int q = 0; q < 2; q++) {
        unsigned long long o = __shfl_xor_sync(0xffffffffu, acc[q], 16);
        add2(acc[q], o);
    }
    if (hi == 0) {
        float2 a0 = unpack2(acc[0]);
        float2 a1 = unpack2(acc[1]);
        float4* pr = reinterpret_cast<float4*>(g_P + (size_t)gw * 64) + sub;
        float4 p = *pr;
        p.x += a0.x; p.y += a0.y; p.z += a1.x; p.w += a1.y;
        *pr = p;
        if (sub == 0) g_mark[gw] = 0;   // self-clean
    }
}

// ---------------- output gather + cursor cleanup --------------------------------
__global__ void gather_out_kernel(const int* __restrict__ idx,
                                  float* __restrict__ out) {
    int i = blockIdx.x * blockDim.x + threadIdx.x;
    if (i < NN) g_cursor[i] = 0;           // self-clean for next launch
    if (i >= NIDX * 16) return;
    int n = i >> 4, f4 = i & 15;
    int r = idx[n];
    reinterpret_cast<float4*>(out + (size_t)n * 64)[f4] =
        reinterpret_cast<const float4*>(g_P + (size_t)r * 64)[f4];
}

// ---------------- fp16 tensor-core GEMM: 3-stage cp.async + ldmatrix ------------
// A: fp16 [M][lda] row-major.  B: fp16 [Ntot][ldb] n-major (K contiguous).
// WN=32 tiles -> 32 accumulator regs/thread -> 3 CTAs/SM.
template <int BM, int BN, int BK, int WM, int WN, bool RELU, bool ADD_BIAS, bool HALF_OUT>
__global__ __launch_bounds__((BM / WM) * (BN / WN) * 32, 3)
void gemm_f16_kernel(const __half* __restrict__ A, int lda,
                     const __half* __restrict__ B, int ldb,
                     const float* __restrict__ bias,
                     void* __restrict__ Cv, int ldc,
                     int M, int Ktot) {
    constexpr int WARPS_M = BM / WM;
    constexpr int WARPS_N = BN / WN;
    constexpr int THREADS = WARPS_M * WARPS_N * 32;
    constexpr int MT = WM / 16;
    constexpr int NT = WN / 8;
    constexpr int LDS = BK + 8;          // halves; 80B stride -> conflict-free ldmatrix
    constexpr int HP = BK / 8;           // 16B chunks per row
    constexpr int A_IT = BM * HP / THREADS;
    constexpr int B_IT = (BN * HP + THREADS - 1) / THREADS;
    constexpr int STAGES = 3;

    __shared__ __half As[STAGES][BM][LDS];
    __shared__ __half Bs[STAGES][BN][LDS];

    int tid = threadIdx.x;
    int lane = tid & 31, wid = tid >> 5;
    int gid = lane >> 2;
    int tig2 = (lane & 3) * 2;
    int wm = (wid / WARPS_N) * WM;
    int wn = (wid % WARPS_N) * WN;
    int m0 = blockIdx.y * BM;
    int n0 = blockIdx.x * BN;

    uint32_t as_base = (uint32_t)__cvta_generic_to_shared(&As[0][0][0]);
    uint32_t bs_base = (uint32_t)__cvta_generic_to_shared(&Bs[0][0][0]);
    constexpr uint32_t A_STAGE = BM * LDS * 2;   // bytes
    constexpr uint32_t B_STAGE = BN * LDS * 2;

    // ldmatrix lane address offsets (bytes within a stage)
    uint32_t offA[MT];
    #pragma unroll
    for (int mt = 0; mt < MT; mt++) {
        int r = wm + mt * 16 + (lane & 7) + ((lane >> 3) & 1) * 8;
        int c = (lane >> 4) * 8;
        offA[mt] = (uint32_t)((r * LDS + c) * 2);
    }
    uint32_t offB[NT / 2];
    #pragma unroll
    for (int nt2 = 0; nt2 < NT / 2; nt2++) {
        int r = wn + nt2 * 16 + (lane & 7) + (lane >> 4) * 8;
        int c = ((lane >> 3) & 1) * 8;
        offB[nt2] = (uint32_t)((r * LDS + c) * 2);
    }

    float acc[MT][NT][4];
    #pragma unroll
    for (int mt = 0; mt < MT; mt++)
        #pragma unroll
        for (int nt = 0; nt < NT; nt++)
            #pragma unroll
            for (int q = 0; q < 4; q++) acc[mt][nt][q] = 0.f;

    const int T = Ktot / BK;

    auto load_tile = [&](int t, int st) {
        int k0 = t * BK;
        #pragma unroll
        for (int it = 0; it < A_IT; it++) {
            int g = tid + it * THREADS;
            int r = g / HP, c = (g % HP) * 8;
            int m = m0 + r;
            int sz = (m < M) ? 16 : 0;
            int mc = (m < M) ? m : 0;
            cp_async16(as_base + st * A_STAGE + (uint32_t)((r * LDS + c) * 2),
                       A + (size_t)mc * lda + k0 + c, sz);
        }
        #pragma unroll
        for (int it = 0; it < B_IT; it++) {
            int g = tid + it * THREADS;
            if (g < BN * HP) {
                int r = g / HP, c = (g % HP) * 8;
                cp_async16(bs_base + st * B_STAGE + (uint32_t)((r * LDS + c) * 2),
                           B + (size_t)(n0 + r) * ldb + k0 + c, 16);
            }
        }
        cp_commit();
    };

    load_tile(0, 0);
    if (T > 1) load_tile(1, 1);
    for (int t = 0; t < T; t++) {
        int st = t % STAGES;
        if (t + 2 < T) {
            load_tile(t + 2, (t + 2) % STAGES);
            cp_wait<2>();
        } else if (t + 1 < T) {
            cp_wait<1>();
        } else {
            cp_wait<0>();
        }
        __syncthreads();

        #pragma unroll
        for (int kk = 0; kk < BK; kk += 16) {
            uint32_t af[MT][4], bf[NT][2];
            #pragma unroll
            for (int mt = 0; mt < MT; mt++) {
                uint32_t addr = as_base + st * A_STAGE + offA[mt] + kk * 2;
                asm volatile(
                    "ldmatrix.sync.aligned.m8n8.x4.shared.b16 {%0,%1,%2,%3}, [%4];"
                    : "=r"(af[mt][0]), "=r"(af[mt][1]),
                      "=r"(af[mt][2]), "=r"(af[mt][3]) : "r"(addr));
            }
            #pragma unroll
            for (int nt2 = 0; nt2 < NT / 2; nt2++) {
                uint32_t addr = bs_base + st * B_STAGE + offB[nt2] + kk * 2;
                asm volatile(
                    "ldmatrix.sync.aligned.m8n8.x4.shared.b16 {%0,%1,%2,%3}, [%4];"
                    : "=r"(bf[2 * nt2][0]), "=r"(bf[2 * nt2][1]),
                      "=r"(bf[2 * nt2 + 1][0]), "=r"(bf[2 * nt2 + 1][1]) : "r"(addr));
            }
            #pragma unroll
            for (int mt = 0; mt < MT; mt++)
                #pragma unroll
                for (int nt = 0; nt < NT; nt++)
                    asm volatile(
                        "mma.sync.aligned.m16n8k16.row.col.f32.f16.f16.f32 "
                        "{%0,%1,%2,%3}, {%4,%5,%6,%7}, {%8,%9}, {%0,%1,%2,%3};"
                        : "+f"(acc[mt][nt][0]), "+f"(acc[mt][nt][1]),
                          "+f"(acc[mt][nt][2]), "+f"(acc[mt][nt][3])
                        : "r"(af[mt][0]), "r"(af[mt][1]), "r"(af[mt][2]), "r"(af[mt][3]),
                          "r"(bf[nt][0]), "r"(bf[nt][1]));
        }
        __syncthreads();
    }

    #pragma unroll
    for (int mt = 0; mt < MT; mt++) {
        int r0 = m0 + wm + mt * 16 + gid;
        #pragma unroll
        for (int nt = 0; nt < NT; nt++) {
            int n = n0 + wn + nt * 8 + tig2;
            float bx = 0.f, by = 0.f;
            if (ADD_BIAS) { bx = bias[n]; by = bias[n + 1]; }
            float2 o0, o1;
            o0.x = acc[mt][nt][0] + bx; o0.y = acc[mt][nt][1] + by;
            o1.x = acc[mt][nt][2] + bx; o1.y = acc[mt][nt][3] + by;
            if (RELU) {
                o0.x = fmaxf(o0.x, 0.f); o0.y = fmaxf(o0.y, 0.f);
                o1.x = fmaxf(o1.x, 0.f); o1.y = fmaxf(o1.y, 0.f);
            }
            if (HALF_OUT) {
                __half* C = (__half*)Cv;
                if (r0 < M)
                    *reinterpret_cast<__half2*>(C + (size_t)r0 * ldc + n) =
                        __floats2half2_rn(o0.x, o0.y);
                if (r0 + 8 < M)
                    *reinterpret_cast<__half2*>(C + (size_t)(r0 + 8) * ldc + n) =
                        __floats2half2_rn(o1.x, o1.y);
            } else {
                float* C = (float*)Cv;
                if (r0 < M)
                    *reinterpret_cast<float2*>(C + (size_t)r0 * ldc + n) = o0;
                if (r0 + 8 < M)
                    *reinterpret_cast<float2*>(C + (size_t)(r0 + 8) * ldc + n) = o1;
            }
        }
    }
}

// ---------------- launch ----------------------------------------------------------
extern "C" void kernel_launch(void* const* d_in, const int* in_sizes, int n_in,
                              void* d_out, int out_size) {
    const float* x    = (const float*)d_in[0];
    const float* vals = (const float*)d_in[1];
    const float* W1   = (const float*)d_in[2];
    const float* b1   = (const float*)d_in[3];
    const float* W2   = (const float*)d_in[4];
    const float* b2   = (const float*)d_in[5];
    const int*   rows = (const int*)d_in[6];
    const int*   cols = (const int*)d_in[7];
    const int*   idx  = (const int*)d_in[8];
    float*       out  = (float*)d_out;

    float  *p;
    __half *bh, *hh, *zh, *w1t, *w2catT, *w2dT;
    cudaGetSymbolAddress((void**)&p,      g_P);
    cudaGetSymbolAddress((void**)&bh,     g_Bh);
    cudaGetSymbolAddress((void**)&hh,     g_Hh);
    cudaGetSymbolAddress((void**)&zh,     g_Zh);
    cudaGetSymbolAddress((void**)&w1t,    g_W1t);
    cudaGetSymbolAddress((void**)&w2catT, g_W2catT);
    cudaGetSymbolAddress((void**)&w2dT,   g_W2dT);

    int warp_blocks = cdiv(NN * 32, 256);

    // 0: bucket scatter + x->fp16 + weight prep + mark output rows
    scatter_prep_kernel<<<cdiv(NNZE, 256), 256>>>(rows, cols, vals, x, W1, W2, idx);
    // 1: T1 = L x
    spmm_bh_kernel<false><<<warp_blocks, 256>>>(0, 128);
    // 2: T2 = 2 L T1 - x
    spmm_bh_kernel<true><<<warp_blocks, 256>>>(128, 256);
    // 3: H = relu(Basis @ W1 + b1) -> fp16   (profiled launch)
    {
        dim3 grid(4, cdiv(NN, 128));   // 4 n-blocks of 64; adjacent CTAs share A tile
        gemm_f16_kernel<128, 64, 32, 32, 32, true, true, true><<<grid, 256>>>(
            bh, 384, w1t, 384, b1, hh, 256, NN, 384);
    }
    // 4: Z = H @ [W2_1 | W2_2] -> fp16
    {
        dim3 grid(2, cdiv(NN, 128));
        gemm_f16_kernel<128, 64, 32, 32, 32, false, false, true><<<grid, 256>>>(
            hh, 256, w2catT, 256, nullptr, zh, 128, NN, 256);
    }
    // 5: P = H @ (W2_0 - W2_2) + b2 -> fp32
    {
        dim3 grid(1, cdiv(NN, 128));
        gemm_f16_kernel<128, 64, 32, 32, 32, false, true, false><<<grid, 256>>>(
            hh, 256, w2dT, 256, b2, p, 64, NN, 256);
    }
    // 6: Q = U + 2 * (L V)
    spmm_q_kernel<<<warp_blocks, 256>>>();
    // 7: marked rows: P[r] += sum v * Q[col]   (clears marks)
    final_rows_kernel<<<warp_blocks, 256>>>();
    // 8: out[i] = P[idx[i]]  (+ cursor cleanup)
    gather_out_kernel<<<cdiv(NIDX * 16, 256), 256>>>(idx, out);
}

// round 17
// speedup vs baseline: 1.0583x; 1.0583x over previous
#include <cuda_runtime.h>
#include <cuda_fp16.h>
#include <cstdint>

#define NN   100000
#define NNZE 3200000
#define NIDX 50000
#define BKT  128          // bucket capacity per row (max degree ~60)

static inline int cdiv(int a, int b) { return (a + b - 1) / b; }

// ---------------- scratch (device globals; zero-initialized at module load) ----
__device__ int    g_cursor[NN];     // degree counters; cleared in gather_out
__device__ int    g_mark[NN];       // set in scatter_prep, cleared by final_rows
__device__ int4   g_bkt4[(size_t)NN * (BKT / 2)];   // 2 edges per int4; unused = 0
// fp16 basis: [N][384] = [x | T1 | T2]
__device__ __half g_Bh[(size_t)NN * 384];
// fp16 hidden: [N][256]
__device__ __half g_Hh[(size_t)NN * 256];
// fp16 Z: [N][128]  ([0:64)=U, [64:128)=V)
__device__ __half g_Zh[(size_t)NN * 128];
// fp16 Q = U + 2*(L V): [N][64]
__device__ __half g_Qh[(size_t)NN * 64];
// P = H @ (W2_0 - W2_2) + b2, fp32; final pass accumulates in place
__device__ float  g_P[(size_t)NN * 64];
// fp16 transposed weights (n-major, K contiguous)
__device__ __half g_W1t[256 * 384];
// W2all rows 0-127 = [W2_1 | W2_2] cols, rows 128-191 = (W2_0 - W2_2)
__device__ __half g_W2all[192 * 256];

// ---------------- packed f32x2 helpers ---------------------------------------
__device__ __forceinline__ unsigned long long pack2(float v) {
    unsigned long long r;
    asm("mov.b64 %0, {%1, %1};" : "=l"(r) : "f"(v));
    return r;
}
__device__ __forceinline__ unsigned long long h2f2(uint32_t h) {
    unsigned long long r;
    asm("{\n\t"
        ".reg .b16 l, h;\n\t"
        ".reg .f32 fl, fh;\n\t"
        "mov.b32 {l, h}, %1;\n\t"
        "cvt.f32.f16 fl, l;\n\t"
        "cvt.f32.f16 fh, h;\n\t"
        "mov.b64 %0, {fl, fh};\n\t"
        "}" : "=l"(r) : "r"(h));
    return r;
}
__device__ __forceinline__ void fma2(unsigned long long& acc,
                                     unsigned long long a, unsigned long long b) {
    asm("fma.rn.f32x2 %0, %1, %2, %0;" : "+l"(acc) : "l"(a), "l"(b));
}
__device__ __forceinline__ void add2(unsigned long long& a, unsigned long long b) {
    asm("add.rn.f32x2 %0, %0, %1;" : "+l"(a) : "l"(b));
}
__device__ __forceinline__ float2 unpack2(unsigned long long a) {
    float2 f;
    asm("mov.b64 {%0, %1}, %2;" : "=f"(f.x), "=f"(f.y) : "l"(a));
    return f;
}
__device__ __forceinline__ uint2 f4_to_h4(float4 v) {
    __half2 h0 = __floats2half2_rn(v.x, v.y);
    __half2 h1 = __floats2half2_rn(v.z, v.w);
    uint2 u;
    u.x = *reinterpret_cast<uint32_t*>(&h0);
    u.y = *reinterpret_cast<uint32_t*>(&h1);
    return u;
}

// ---------------- cp.async helpers --------------------------------------------
__device__ __forceinline__ void cp_async16(uint32_t dst, const void* src, int sz) {
    asm volatile("cp.async.ca.shared.global [%0], [%1], 16, %2;"
                 :: "r"(dst), "l"(src), "r"(sz));
}
__device__ __forceinline__ void cp_commit() {
    asm volatile("cp.async.commit_group;");
}
template <int NWAIT>
__device__ __forceinline__ void cp_wait() {
    asm volatile("cp.async.wait_group %0;" :: "n"(NWAIT));
}

// ---------------- scatter + x->fp16 + weight prep + marking (one launch) -------
__global__ void scatter_prep_kernel(const int* __restrict__ rows,
                                    const int* __restrict__ cols,
                                    const float* __restrict__ vals,
                                    const float* __restrict__ x,
                                    const float* __restrict__ W1,
                                    const float* __restrict__ W2,
                                    const int* __restrict__ idx) {
    int i = blockIdx.x * blockDim.x + threadIdx.x;
    if (i < NNZE) {
        int r = rows[i];
        int pos = atomicAdd(&g_cursor[r], 1);
        reinterpret_cast<int2*>(g_bkt4)[(size_t)r * BKT + pos] =
            make_int2(cols[i], __float_as_int(vals[i]));
    }
    if (i < NN * 32) {
        int n = i >> 5, f4 = i & 31;
        float4 v = reinterpret_cast<const float4*>(x)[i];
        reinterpret_cast<uint2*>(g_Bh + (size_t)n * 384)[f4] = f4_to_h4(v);
    }
    if (i < 256 * 384) {              // W1t[j][t], t = k*128+f
        int j = i / 384, t = i % 384;
        int k = t / 128, f = t % 128;
        g_W1t[i] = __float2half(W1[(f * 3 + k) * 256 + j]);
    }
    if (i < 192 * 256) {              // W2all[j][f]
        int j = i / 256, f = i % 256;
        float w;
        if (j < 64)       w = W2[(f * 3 + 1) * 64 + j];
        else if (j < 128) w = W2[(f * 3 + 2) * 64 + (j - 64)];
        else              w = W2[(f * 3 + 0) * 64 + (j - 128)] -
                              W2[(f * 3 + 2) * 64 + (j - 128)];
        g_W2all[i] = __float2half(w);
    }
    if (i < NIDX) g_mark[idx[i]] = 1;
}

// ---------------- SpMM over fp16 basis: half-warp edge pairing -----------------
template <bool SUB>
__global__ void spmm_bh_kernel(int src_off, int dst_off) {
    int gw = (blockIdx.x * blockDim.x + threadIdx.x) >> 5;
    if (gw >= NN) return;
    int lane = threadIdx.x & 31;
    int hi = lane >> 4;          // which edge of each pair
    int sub = lane & 15;         // 16B feature slice
    int n = g_cursor[gw];
    const int4* b4 = g_bkt4 + (size_t)gw * (BKT / 2);

    unsigned long long acc[4] = {0ull, 0ull, 0ull, 0ull};

    int iters = (n + 7) >> 3;    // buckets zero-padded -> no tail loop
    for (int it = 0; it < iters; it++) {
        int4 e[4];
        #pragma unroll
        for (int q = 0; q < 4; q++) e[q] = b4[it * 4 + q];
        #pragma unroll
        for (int q = 0; q < 4; q++) {
            int col   = hi ? e[q].z : e[q].x;
            int vbits = hi ? e[q].w : e[q].y;
            uint4 u = *reinterpret_cast<const uint4*>(
                g_Bh + (size_t)col * 384 + src_off + sub * 8);
            unsigned long long v2 = pack2(__int_as_float(vbits));
            fma2(acc[0], h2f2(u.x), v2);
            fma2(acc[1], h2f2(u.y), v2);
            fma2(acc[2], h2f2(u.z), v2);
            fma2(acc[3], h2f2(u.w), v2);
        }
    }
    #pragma unroll
    for (int q = 0; q < 4; q++) {
        unsigned long long o = __shfl_xor_sync(0xffffffffu, acc[q], 16);
        add2(acc[q], o);
    }
    if (hi == 0) {
        float f[8];
        #pragma unroll
        for (int q = 0; q < 4; q++) {
            float2 t = unpack2(acc[q]);
            f[2 * q] = t.x; f[2 * q + 1] = t.y;
        }
        if (SUB) {
            uint4 su = *reinterpret_cast<const uint4*>(
                g_Bh + (size_t)gw * 384 + sub * 8);
            const __half* sh = reinterpret_cast<const __half*>(&su);
            #pragma unroll
            for (int q = 0; q < 8; q++)
                f[q] = 2.f * f[q] - __half2float(sh[q]);
        }
        uint4 o;
        __half2 h0 = __floats2half2_rn(f[0], f[1]);
        __half2 h1 = __floats2half2_rn(f[2], f[3]);
        __half2 h2 = __floats2half2_rn(f[4], f[5]);
        __half2 h3 = __floats2half2_rn(f[6], f[7]);
        o.x = *reinterpret_cast<uint32_t*>(&h0);
        o.y = *reinterpret_cast<uint32_t*>(&h1);
        o.z = *reinterpret_cast<uint32_t*>(&h2);
        o.w = *reinterpret_cast<uint32_t*>(&h3);
        *reinterpret_cast<uint4*>(g_Bh + (size_t)gw * 384 + dst_off + sub * 8) = o;
    }
}

// ---------------- Q = U + 2*(L V): rows 64 halves (128B), paired edges ---------
__global__ void spmm_q_kernel() {
    int gw = (blockIdx.x * blockDim.x + threadIdx.x) >> 5;
    if (gw >= NN) return;
    int lane = threadIdx.x & 31;
    int hi = lane >> 4;
    int sub = lane & 15;         // 8B slice (4 halves)
    int n = g_cursor[gw];
    const int4* b4 = g_bkt4 + (size_t)gw * (BKT / 2);

    unsigned long long acc[2] = {0ull, 0ull};
    int iters = (n + 7) >> 3;
    for (int it = 0; it < iters; it++) {
        int4 e[4];
        #pragma unroll
        for (int q = 0; q < 4; q++) e[q] = b4[it * 4 + q];
        #pragma unroll
        for (int q = 0; q < 4; q++) {
            int col   = hi ? e[q].z : e[q].x;
            int vbits = hi ? e[q].w : e[q].y;
            uint2 u = *reinterpret_cast<const uint2*>(
                g_Zh + (size_t)col * 128 + 64 + sub * 4);
            unsigned long long v2 = pack2(__int_as_float(vbits));
            fma2(acc[0], h2f2(u.x), v2);
            fma2(acc[1], h2f2(u.y), v2);
        }
    }
    #pragma unroll
    for (int q = 0; q < 2; q++) {
        unsigned long long o = __shfl_xor_sync(0xffffffffu, acc[q], 16);
        add2(acc[q], o);
    }
    if (hi == 0) {
        float2 a0 = unpack2(acc[0]);
        float2 a1 = unpack2(acc[1]);
        uint2 uu = *reinterpret_cast<const uint2*>(
            g_Zh + (size_t)gw * 128 + sub * 4);
        const __half* uh = reinterpret_cast<const __half*>(&uu);
        __half2 h0 = __floats2half2_rn(__half2float(uh[0]) + 2.f * a0.x,
                                       __half2float(uh[1]) + 2.f * a0.y);
        __half2 h1 = __floats2half2_rn(__half2float(uh[2]) + 2.f * a1.x,
                                       __half2float(uh[3]) + 2.f * a1.y);
        uint2 o;
        o.x = *reinterpret_cast<uint32_t*>(&h0);
        o.y = *reinterpret_cast<uint32_t*>(&h1);
        *reinterpret_cast<uint2*>(g_Qh + (size_t)gw * 64 + sub * 4) = o;
    }
}

// ---------------- final: marked rows, P[r] += sum v*Q[col]; clear mark ----------
__global__ void final_rows_kernel() {
    int gw = (blockIdx.x * blockDim.x + threadIdx.x) >> 5;
    if (gw >= NN) return;
    if (g_mark[gw] == 0) return;
    int lane = threadIdx.x & 31;
    int hi = lane >> 4;
    int sub = lane & 15;
    int n = g_cursor[gw];
    const int4* b4 = g_bkt4 + (size_t)gw * (BKT / 2);

    unsigned long long acc[2] = {0ull, 0ull};
    int iters = (n + 7) >> 3;
    for (int it = 0; it < iters; it++) {
        int4 e[4];
        #pragma unroll
        for (int q = 0; q < 4; q++) e[q] = b4[it * 4 + q];
        #pragma unroll
        for (int q = 0; q < 4; q++) {
            int col   = hi ? e[q].z : e[q].x;
            int vbits = hi ? e[q].w : e[q].y;
            uint2 u = *reinterpret_cast<const uint2*>(
                g_Qh + (size_t)col * 64 + sub * 4);
            unsigned long long v2 = pack2(__int_as_float(vbits));
            fma2(acc[0], h2f2(u.x), v2);
            fma2(acc[1], h2f2(u.y), v2);
        }
    }
    #pragma unroll
    for (int q = 0; q < 2; q++) {
        unsigned long long o = __shfl_xor_sync(0xffffffffu, acc[q], 16);
        add2(acc[q], o);
    }
    if (hi == 0) {
        float2 a0 = unpack2(acc[0]);
        float2 a1 = unpack2(acc[1]);
        float4* pr = reinterpret_cast<float4*>(g_P + (size_t)gw * 64) + sub;
        float4 p = *pr;
        p.x += a0.x; p.y += a0.y; p.z += a1.x; p.w += a1.y;
        *pr = p;
        if (sub == 0) g_mark[gw] = 0;   // self-clean
    }
}

// ---------------- output gather + cursor cleanup --------------------------------
__global__ void gather_out_kernel(const int* __restrict__ idx,
                                  float* __restrict__ out) {
    int i = blockIdx.x * blockDim.x + threadIdx.x;
    if (i < NN) g_cursor[i] = 0;           // self-clean for next launch
    if (i >= NIDX * 16) return;
    int n = i >> 4, f4 = i & 15;
    int r = idx[n];
    reinterpret_cast<float4*>(out + (size_t)n * 64)[f4] =
        reinterpret_cast<const float4*>(g_P + (size_t)r * 64)[f4];
}

// ---------------- fp16 tensor-core GEMM: 2-stage cp.async + ldmatrix ------------
// (round-14 proven config: BM=128, BN=128, WM=32, WN=64)
// A: fp16 [M][lda] row-major.  B: fp16 [Ntot][ldb] n-major (K contiguous).
template <int BM, int BN, int BK, int WM, int WN, bool RELU, bool ADD_BIAS, bool HALF_OUT>
__global__ __launch_bounds__((BM / WM) * (BN / WN) * 32)
void gemm_f16_kernel(const __half* __restrict__ A, int lda,
                     const __half* __restrict__ B, int ldb,
                     const float* __restrict__ bias,
                     void* __restrict__ Cv, int ldc,
                     int M, int Ktot) {
    constexpr int WARPS_M = BM / WM;
    constexpr int WARPS_N = BN / WN;
    constexpr int THREADS = WARPS_M * WARPS_N * 32;
    constexpr int MT = WM / 16;
    constexpr int NT = WN / 8;
    constexpr int LDS = BK + 8;
    constexpr int HP = BK / 8;
    constexpr int A_IT = BM * HP / THREADS;
    constexpr int B_IT = (BN * HP + THREADS - 1) / THREADS;

    __shared__ __half As[2][BM][LDS];
    __shared__ __half Bs[2][BN][LDS];

    int tid = threadIdx.x;
    int lane = tid & 31, wid = tid >> 5;
    int gid = lane >> 2;
    int tig2 = (lane & 3) * 2;
    int wm = (wid / WARPS_N) * WM;
    int wn = (wid % WARPS_N) * WN;
    int m0 = blockIdx.y * BM;
    int n0 = blockIdx.x * BN;

    uint32_t as_base = (uint32_t)__cvta_generic_to_shared(&As[0][0][0]);
    uint32_t bs_base = (uint32_t)__cvta_generic_to_shared(&Bs[0][0][0]);
    constexpr uint32_t A_STAGE = BM * LDS * 2;
    constexpr uint32_t B_STAGE = BN * LDS * 2;

    uint32_t offA[MT];
    #pragma unroll
    for (int mt = 0; mt < MT; mt++) {
        int r = wm + mt * 16 + (lane & 7) + ((lane >> 3) & 1) * 8;
        int c = (lane >> 4) * 8;
        offA[mt] = (uint32_t)((r * LDS + c) * 2);
    }
    uint32_t offB[NT / 2];
    #pragma unroll
    for (int nt2 = 0; nt2 < NT / 2; nt2++) {
        int r = wn + nt2 * 16 + (lane & 7) + (lane >> 4) * 8;
        int c = ((lane >> 3) & 1) * 8;
        offB[nt2] = (uint32_t)((r * LDS + c) * 2);
    }

    float acc[MT][NT][4];
    #pragma unroll
    for (int mt = 0; mt < MT; mt++)
        #pragma unroll
        for (int nt = 0; nt < NT; nt++)
            #pragma unroll
            for (int q = 0; q < 4; q++) acc[mt][nt][q] = 0.f;

    const int T = Ktot / BK;

    auto load_tile = [&](int t, int st) {
        int k0 = t * BK;
        #pragma unroll
        for (int it = 0; it < A_IT; it++) {
            int g = tid + it * THREADS;
            int r = g / HP, c = (g % HP) * 8;
            int m = m0 + r;
            int sz = (m < M) ? 16 : 0;
            int mc = (m < M) ? m : 0;
            cp_async16(as_base + st * A_STAGE + (uint32_t)((r * LDS + c) * 2),
                       A + (size_t)mc * lda + k0 + c, sz);
        }
        #pragma unroll
        for (int it = 0; it < B_IT; it++) {
            int g = tid + it * THREADS;
            if (g < BN * HP) {
                int r = g / HP, c = (g % HP) * 8;
                cp_async16(bs_base + st * B_STAGE + (uint32_t)((r * LDS + c) * 2),
                           B + (size_t)(n0 + r) * ldb + k0 + c, 16);
            }
        }
        cp_commit();
    };

    load_tile(0, 0);
    for (int t = 0; t < T; t++) {
        int st = t & 1;
        if (t + 1 < T) {
            load_tile(t + 1, st ^ 1);
            cp_wait<1>();
        } else {
            cp_wait<0>();
        }
        __syncthreads();

        #pragma unroll
        for (int kk = 0; kk < BK; kk += 16) {
            uint32_t af[MT][4], bf[NT][2];
            #pragma unroll
            for (int mt = 0; mt < MT; mt++) {
                uint32_t addr = as_base + st * A_STAGE + offA[mt] + kk * 2;
                asm volatile(
                    "ldmatrix.sync.aligned.m8n8.x4.shared.b16 {%0,%1,%2,%3}, [%4];"
                    : "=r"(af[mt][0]), "=r"(af[mt][1]),
                      "=r"(af[mt][2]), "=r"(af[mt][3]) : "r"(addr));
            }
            #pragma unroll
            for (int nt2 = 0; nt2 < NT / 2; nt2++) {
                uint32_t addr = bs_base + st * B_STAGE + offB[nt2] + kk * 2;
                asm volatile(
                    "ldmatrix.sync.aligned.m8n8.x4.shared.b16 {%0,%1,%2,%3}, [%4];"
                    : "=r"(bf[2 * nt2][0]), "=r"(bf[2 * nt2][1]),
                      "=r"(bf[2 * nt2 + 1][0]), "=r"(bf[2 * nt2 + 1][1]) : "r"(addr));
            }
            #pragma unroll
            for (int mt = 0; mt < MT; mt++)
                #pragma unroll
                for (int nt = 0; nt < NT; nt++)
                    asm volatile(
                        "mma.sync.aligned.m16n8k16.row.col.f32.f16.f16.f32 "
                        "{%0,%1,%2,%3}, {%4,%5,%6,%7}, {%8,%9}, {%0,%1,%2,%3};"
                        : "+f"(acc[mt][nt][0]), "+f"(acc[mt][nt][1]),
                          "+f"(acc[mt][nt][2]), "+f"(acc[mt][nt][3])
                        : "r"(af[mt][0]), "r"(af[mt][1]), "r"(af[mt][2]), "r"(af[mt][3]),
                          "r"(bf[nt][0]), "r"(bf[nt][1]));
        }
        __syncthreads();
    }

    #pragma unroll
    for (int mt = 0; mt < MT; mt++) {
        int r0 = m0 + wm + mt * 16 + gid;
        #pragma unroll
        for (int nt = 0; nt < NT; nt++) {
            int n = n0 + wn + nt * 8 + tig2;
            float bx = 0.f, by = 0.f;
            if (ADD_BIAS) { bx = bias[n]; by = bias[n + 1]; }
            float2 o0, o1;
            o0.x = acc[mt][nt][0] + bx; o0.y = acc[mt][nt][1] + by;
            o1.x = acc[mt][nt][2] + bx; o1.y = acc[mt][nt][3] + by;
            if (RELU) {
                o0.x = fmaxf(o0.x, 0.f); o0.y = fmaxf(o0.y, 0.f);
                o1.x = fmaxf(o1.x, 0.f); o1.y = fmaxf(o1.y, 0.f);
            }
            if (HALF_OUT) {
                __half* C = (__half*)Cv;
                if (r0 < M)
                    *reinterpret_cast<__half2*>(C + (size_t)r0 * ldc + n) =
                        __floats2half2_rn(o0.x, o0.y);
                if (r0 + 8 < M)
                    *reinterpret_cast<__half2*>(C + (size_t)(r0 + 8) * ldc + n) =
                        __floats2half2_rn(o1.x, o1.y);
            } else {
                float* C = (float*)Cv;
                if (r0 < M)
                    *reinterpret_cast<float2*>(C + (size_t)r0 * ldc + n) = o0;
                if (r0 + 8 < M)
                    *reinterpret_cast<float2*>(C + (size_t)(r0 + 8) * ldc + n) = o1;
            }
        }
    }
}

// ---------------- fused Z+P GEMM ------------------------------------------------
// A = Hh [M][256]; B = W2all [192][256] n-major. n-blocks of 64:
//   blockIdx.x 0,1 -> Z fp16 (cols 0..127), blockIdx.x 2 -> P fp32 + b2.
__global__ __launch_bounds__(128)
void gemm_zp_kernel(const __half* __restrict__ A,
                    const __half* __restrict__ B,
                    const float* __restrict__ b2,
                    __half* __restrict__ Z, float* __restrict__ P, int M) {
    constexpr int BM = 128, BN = 64, BK = 32;
    constexpr int THREADS = 128;         // 4 warps stacked in M; WN=64 per warp
    constexpr int MT = 2, NT = 8;
    constexpr int LDS = BK + 8;
    constexpr int HP = BK / 8;
    constexpr int A_IT = BM * HP / THREADS;   // 4
    constexpr int B_IT = BN * HP / THREADS;   // 2

    __shared__ __half As[2][BM][LDS];
    __shared__ __half Bs[2][BN][LDS];

    int tid = threadIdx.x;
    int lane = tid & 31, wid = tid >> 5;
    int gid = lane >> 2;
    int tig2 = (lane & 3) * 2;
    int wm = wid * 32;                    // 4 warps cover M 0..127
    int m0 = blockIdx.y * BM;
    int n0 = blockIdx.x * BN;             // 0, 64, 128

    uint32_t as_base = (uint32_t)__cvta_generic_to_shared(&As[0][0][0]);
    uint32_t bs_base = (uint32_t)__cvta_generic_to_shared(&Bs[0][0][0]);
    constexpr uint32_t A_STAGE = BM * LDS * 2;
    constexpr uint32_t B_STAGE = BN * LDS * 2;

    uint32_t offA[MT];
    #pragma unroll
    for (int mt = 0; mt < MT; mt++) {
        int r = wm + mt * 16 + (lane & 7) + ((lane >> 3) & 1) * 8;
        int c = (lane >> 4) * 8;
        offA[mt] = (uint32_t)((r * LDS + c) * 2);
    }
    uint32_t offB[NT / 2];
    #pragma unroll
    for (int nt2 = 0; nt2 < NT / 2; nt2++) {
        int r = nt2 * 16 + (lane & 7) + (lane >> 4) * 8;
        int c = ((lane >> 3) & 1) * 8;
        offB[nt2] = (uint32_t)((r * LDS + c) * 2);
    }

    float acc[MT][NT][4];
    #pragma unroll
    for (int mt = 0; mt < MT; mt++)
        #pragma unroll
        for (int nt = 0; nt < NT; nt++)
            #pragma unroll
            for (int q = 0; q < 4; q++) acc[mt][nt][q] = 0.f;

    const int T = 256 / BK;   // 8

    auto load_tile = [&](int t, int st) {
        int k0 = t * BK;
        #pragma unroll
        for (int it = 0; it < A_IT; it++) {
            int g = tid + it * THREADS;
            int r = g / HP, c = (g % HP) * 8;
            int m = m0 + r;
            int sz = (m < M) ? 16 : 0;
            int mc = (m < M) ? m : 0;
            cp_async16(as_base + st * A_STAGE + (uint32_t)((r * LDS + c) * 2),
                       A + (size_t)mc * 256 + k0 + c, sz);
        }
        #pragma unroll
        for (int it = 0; it < B_IT; it++) {
            int g = tid + it * THREADS;
            int r = g / HP, c = (g % HP) * 8;
            cp_async16(bs_base + st * B_STAGE + (uint32_t)((r * LDS + c) * 2),
                       B + (size_t)(n0 + r) * 256 + k0 + c, 16);
        }
        cp_commit();
    };

    load_tile(0, 0);
    for (int t = 0; t < T; t++) {
        int st = t & 1;
        if (t + 1 < T) {
            load_tile(t + 1, st ^ 1);
            cp_wait<1>();
        } else {
            cp_wait<0>();
        }
        __syncthreads();

        #pragma unroll
        for (int kk = 0; kk < BK; kk += 16) {
            uint32_t af[MT][4], bf[NT][2];
            #pragma unroll
            for (int mt = 0; mt < MT; mt++) {
                uint32_t addr = as_base + st * A_STAGE + offA[mt] + kk * 2;
                asm volatile(
                    "ldmatrix.sync.aligned.m8n8.x4.shared.b16 {%0,%1,%2,%3}, [%4];"
                    : "=r"(af[mt][0]), "=r"(af[mt][1]),
                      "=r"(af[mt][2]), "=r"(af[mt][3]) : "r"(addr));
            }
            #pragma unroll
            for (int nt2 = 0; nt2 < NT / 2; nt2++) {
                uint32_t addr = bs_base + st * B_STAGE + offB[nt2] + kk * 2;
                asm volatile(
                    "ldmatrix.sync.aligned.m8n8.x4.shared.b16 {%0,%1,%2,%3}, [%4];"
                    : "=r"(bf[2 * nt2][0]), "=r"(bf[2 * nt2][1]),
                      "=r"(bf[2 * nt2 + 1][0]), "=r"(bf[2 * nt2 + 1][1]) : "r"(addr));
            }
            #pragma unroll
            for (int mt = 0; mt < MT; mt++)
                #pragma unroll
                for (int nt = 0; nt < NT; nt++)
                    asm volatile(
                        "mma.sync.aligned.m16n8k16.row.col.f32.f16.f16.f32 "
                        "{%0,%1,%2,%3}, {%4,%5,%6,%7}, {%8,%9}, {%0,%1,%2,%3};"
                        : "+f"(acc[mt][nt][0]), "+f"(acc[mt][nt][1]),
                          "+f"(acc[mt][nt][2]), "+f"(acc[mt][nt][3])
                        : "r"(af[mt][0]), "r"(af[mt][1]), "r"(af[mt][2]), "r"(af[mt][3]),
                          "r"(bf[nt][0]), "r"(bf[nt][1]));
        }
        __syncthreads();
    }

    bool isP = (n0 >= 128);
    #pragma unroll
    for (int mt = 0; mt < MT; mt++) {
        int r0 = m0 + wm + mt * 16 + gid;
        #pragma unroll
        for (int nt = 0; nt < NT; nt++) {
            int n = n0 + nt * 8 + tig2;
            float2 o0, o1;
            o0.x = acc[mt][nt][0]; o0.y = acc[mt][nt][1];
            o1.x = acc[mt][nt][2]; o1.y = acc[mt][nt][3];
            if (!isP) {
                if (r0 < M)
                    *reinterpret_cast<__half2*>(Z + (size_t)r0 * 128 + n) =
                        __floats2half2_rn(o0.x, o0.y);
                if (r0 + 8 < M)
                    *reinterpret_cast<__half2*>(Z + (size_t)(r0 + 8) * 128 + n) =
                        __floats2half2_rn(o1.x, o1.y);
            } else {
                int np = n - 128;
                float bx = b2[np], by = b2[np + 1];
                o0.x += bx; o0.y += by;
                o1.x += bx; o1.y += by;
                if (r0 < M)
                    *reinterpret_cast<float2*>(P + (size_t)r0 * 64 + np) = o0;
                if (r0 + 8 < M)
                    *reinterpret_cast<float2*>(P + (size_t)(r0 + 8) * 64 + np) = o1;
            }
        }
    }
}

// ---------------- launch ----------------------------------------------------------
extern "C" void kernel_launch(void* const* d_in, const int* in_sizes, int n_in,
                              void* d_out, int out_size) {
    const float* x    = (const float*)d_in[0];
    const float* vals = (const float*)d_in[1];
    const float* W1   = (const float*)d_in[2];
    const float* b1   = (const float*)d_in[3];
    const float* W2   = (const float*)d_in[4];
    const float* b2   = (const float*)d_in[5];
    const int*   rows = (const int*)d_in[6];
    const int*   cols = (const int*)d_in[7];
    const int*   idx  = (const int*)d_in[8];
    float*       out  = (float*)d_out;

    float  *p;
    __half *bh, *hh, *zh, *w1t, *w2all;
    cudaGetSymbolAddress((void**)&p,     g_P);
    cudaGetSymbolAddress((void**)&bh,    g_Bh);
    cudaGetSymbolAddress((void**)&hh,    g_Hh);
    cudaGetSymbolAddress((void**)&zh,    g_Zh);
    cudaGetSymbolAddress((void**)&w1t,   g_W1t);
    cudaGetSymbolAddress((void**)&w2all, g_W2all);

    int warp_blocks = cdiv(NN * 32, 256);

    // 0: bucket scatter + x->fp16 + weight prep + mark output rows
    scatter_prep_kernel<<<cdiv(NNZE, 256), 256>>>(rows, cols, vals, x, W1, W2, idx);
    // 1: T1 = L x
    spmm_bh_kernel<false><<<warp_blocks, 256>>>(0, 128);
    // 2: T2 = 2 L T1 - x
    spmm_bh_kernel<true><<<warp_blocks, 256>>>(128, 256);
    // 3: H = relu(Basis @ W1 + b1) -> fp16   (round-14 config; profiled launch)
    {
        dim3 grid(2, cdiv(NN, 128));
        gemm_f16_kernel<128, 128, 32, 32, 64, true, true, true><<<grid, 256>>>(
            bh, 384, w1t, 384, b1, hh, 256, NN, 384);
    }
    // 4: fused Z (fp16) + P (fp32 + b2) from Hh @ W2all
    {
        dim3 grid(3, cdiv(NN, 128));
        gemm_zp_kernel<<<grid, 128>>>(hh, w2all, b2, zh, p, NN);
    }
    // 5: Q = U + 2 * (L V)
    spmm_q_kernel<<<warp_blocks, 256>>>();
    // 6: marked rows: P[r] += sum v * Q[col]   (clears marks)
    final_rows_kernel<<<warp_blocks, 256>>>();
    // 7: out[i] = P[idx[i]]  (+ cursor cleanup)
    gather_out_kernel<<<cdiv(NIDX * 16, 256), 256>>>(idx, out);
}